// round 16
// baseline (speedup 1.0000x reference)
#include <cuda_runtime.h>
#include <cstdint>

// Batched Thomas tridiagonal solve, B=2048, N=8192, chunked via diagonal
// dominance (alpha in [0,0.3)). Continuant (D/S) recurrence, rcp.approx
// off the dependence chain.
// R15: dual-chain ILP. Each thread's 128-col chunk is split into two 64-col
// sub-chunks (A: cols [s,s+64), B: [s+64,s+128)), each with its own HF=8
// forward halo (cut mid-chunk; contraction 0.097^8 ~ 8e-9) and HB=16 backward
// halo. Staged span is unchanged (153 cols) -> same smem/staging/occupancy as
// the 59us R12 config, but phases 1 and 2 run TWO independent recurrence
// chains per thread, doubling per-warp ILP (R14 proved the kernel is
// dependency-stall bound: warps issue once per ~5 cyc).

#define N_COLSK 8192
#define L_OWN   128
#define HF      8
#define SPAN_C  153                 // HF + 128 + 16 + 1; odd pitch -> conflict-free LDS
#define TPB     128
#define NSUB    5                   // 16-step tiles per sub-chain (tile 4 = halo)
#define TAIL_C  (SPAN_C - TPB)      // 25

#define SM_F    (TPB * SPAN_C)                      // f slice
#define SM_CK   (SM_F + SPAN_C + 3)                 // checkpoints
#define NCKSLOT (2 * NSUB)                          // 10 tile slots (A:0..4, B:5..9)
#define CKDP    (NCKSLOT * TPB)                     // dp array offset after cp
#define SM_DUMP (SM_CK + 2 * NCKSLOT * TPB)
#define SMEM_FLOATS (SM_DUMP + TPB)
#define SMEM_BYTES  (SMEM_FLOATS * 4)               // ~89.8 KB -> 2 blocks/SM

__device__ __forceinline__ float frcp(float x) {
    float r; asm("rcp.approx.f32 %0, %1;" : "=f"(r) : "f"(x)); return r;
}

// cp.async 4B; src_sz = 0 zero-fills the destination (OOB handling).
__device__ __forceinline__ void cpa4(unsigned int saddr, const float* g, int src_sz) {
    asm volatile("cp.async.ca.shared.global [%0], [%1], 4, %2;"
                 :: "r"(saddr), "l"(g), "r"(src_sz));
}

// Forward continuant chain state.
struct Chain { float Dmm, Dm, S, sqim1, sqi, al; };

__device__ __forceinline__ void fstep(Chain& c, float alp1, float fv) {
    float sq1  = alp1 * alp1;
    float bi   = fmaf(c.al, c.sqi, 1.0f);
    float cim1 = fmaf(2.0f, c.al, c.sqi);
    float t    = (c.sqim1 * cim1) * c.Dmm;
    float Dn   = fmaf(bi, c.Dm, -t);
    float Sn   = fmaf(-c.sqim1, c.S, fv * c.Dm);
    c.Dmm = c.Dm; c.Dm = Dn; c.S = Sn;
    c.sqim1 = c.sqi; c.sqi = sq1; c.al = alp1;
}

__device__ __forceinline__ void ckpt(const Chain& c, float* ckS, int slot, int tid) {
    float r    = frcp(c.Dm);
    float cim1 = fmaf(2.0f, c.al, c.sqi);            // c_{base-1}
    ckS[slot * TPB + tid]        = (cim1 * c.Dmm) * r;   // cp_in
    ckS[CKDP + slot * TPB + tid] = c.S * r;              // dp_in
}

// Phase-2 16-step tile: recompute cp/dp from checkpoint, back-substitute.
template<bool STORE>
__device__ __forceinline__ void tile16(
    const float* __restrict__ sA, const float* __restrict__ fS, int base,
    float cp_in, float dp_in, float& u, float* __restrict__ op)
{
    float cpl[16], dpl[16];
    float alm = sA[base - 1];
    float sm1 = alm * alm;                           // a_base
    float dmm, dm, sl, qim1, qi, a2;
    {   // j = 0: fold incoming (cp_in, dp_in); local D~_{-1} = 1
        float al2  = sA[base];
        float sq2  = al2 * al2;
        float alp1 = sA[base + 1];
        float fv   = fS[base];
        float sq1  = alp1 * alp1;
        float bi   = fmaf(al2, sq2, 1.0f);
        float D0   = fmaf(-sm1, cp_in, bi);
        float S0   = fmaf(-sm1, dp_in, fv);
        float r    = frcp(D0);
        float cj   = fmaf(2.0f, alp1, sq1);
        cpl[0] = cj * r;
        dpl[0] = S0 * r;
        dmm = 1.0f; dm = D0; sl = S0;
        qim1 = sq2; qi = sq1; a2 = alp1;
    }
    #pragma unroll
    for (int j = 1; j < 16; ++j) {
        float alp1 = sA[base + j + 1];
        float fv   = fS[base + j];
        float sq1  = alp1 * alp1;
        float bi   = fmaf(a2, qi, 1.0f);
        float cim1 = fmaf(2.0f, a2, qi);
        float t    = (qim1 * cim1) * dmm;
        float dn   = fmaf(bi, dm, -t);
        float sn   = fmaf(-qim1, sl, fv * dm);
        float r    = frcp(dn);
        float cj   = fmaf(2.0f, alp1, sq1);
        cpl[j] = (cj * dm) * r;
        dpl[j] = sn * r;
        dmm = dm; dm = dn; sl = sn;
        qim1 = qi; qi = sq1; a2 = alp1;
    }
    #pragma unroll
    for (int j = 15; j >= 0; --j) {
        u = fmaf(-cpl[j], u, dpl[j]);
        dpl[j] = u;
    }
    if (STORE) {
        float4* o4 = reinterpret_cast<float4*>(op);
        o4[0] = make_float4(dpl[0],  dpl[1],  dpl[2],  dpl[3]);
        o4[1] = make_float4(dpl[4],  dpl[5],  dpl[6],  dpl[7]);
        o4[2] = make_float4(dpl[8],  dpl[9],  dpl[10], dpl[11]);
        o4[3] = make_float4(dpl[12], dpl[13], dpl[14], dpl[15]);
    }
}

__global__ __launch_bounds__(TPB, 2)
void thomas_chunk_kernel(const float* __restrict__ alpha,
                         const float* __restrict__ f,
                         float* __restrict__ out)
{
    extern __shared__ float smem[];
    float* fS  = smem + SM_F;
    float* ckS = smem + SM_CK;

    const int tid  = threadIdx.x;
    const int cc   = blockIdx.x;                 // chunk column (0..63)
    const int row0 = blockIdx.y * TPB;
    const int s    = cc * L_OWN;
    const int col0 = s - HF;                     // first staged col (>= -8)

    // ================= cp.async staging (identical to R12) ==================
    {
        const unsigned int smb  = (unsigned int)__cvta_generic_to_shared(smem);
        const unsigned int dump = smb + (unsigned int)(SM_DUMP + tid) * 4u;

        const int c1 = col0 + tid;                       // cols 0..127
        const int c2 = col0 + TPB + tid;                 // cols 128..152 (tid<25)
        const int sz1 = (c1 >= 0 && c1 < N_COLSK) ? 4 : 0;
        const bool l2 = (tid < TAIL_C);
        const int sz2 = (l2 && c2 < N_COLSK) ? 4 : 0;
        const int c1c = max(0, min(c1, N_COLSK - 1));
        const int c2c = min(c2, N_COLSK - 1);

        const float* g1 = alpha + (size_t)row0 * N_COLSK + c1c;
        const float* g2 = alpha + (size_t)row0 * N_COLSK + c2c;
        unsigned int s1 = smb + (unsigned int)tid * 4u;
        unsigned int s2 = l2 ? (smb + (unsigned int)(TPB + tid) * 4u) : dump;
        const unsigned int step2 = l2 ? (SPAN_C * 4u) : 0u;

        #pragma unroll 4
        for (int r = 0; r < TPB; ++r) {
            cpa4(s1, g1, sz1);
            cpa4(s2, g2, sz2);
            s1 += SPAN_C * 4u;
            s2 += step2;
            g1 += N_COLSK; g2 += N_COLSK;
        }
        const unsigned int fsb = smb + SM_F * 4u;
        cpa4(fsb + (unsigned int)tid * 4u, f + c1c, sz1);
        cpa4(l2 ? (fsb + (unsigned int)(TPB + tid) * 4u) : dump, f + c2c, sz2);

        asm volatile("cp.async.commit_group;");
        asm volatile("cp.async.wait_group 0;");
    }
    __syncthreads();

    const float* sA = smem + tid * SPAN_C;

    // ===== phase 1: DUAL forward sweeps (A at rc=0.., B at rc=64..) =====
    Chain A, Bc;
    A.Dmm = 0.0f; A.Dm = 1.0f; A.S = 0.0f; A.sqim1 = 0.0f;
    A.al = sA[0];  A.sqi = A.al * A.al;
    Bc.Dmm = 0.0f; Bc.Dm = 1.0f; Bc.S = 0.0f; Bc.sqim1 = 0.0f;
    Bc.al = sA[64]; Bc.sqi = Bc.al * Bc.al;

    #pragma unroll
    for (int j = 0; j < HF; ++j) {               // dual halo warmup
        fstep(A,  sA[j + 1],      fS[j]);
        fstep(Bc, sA[64 + j + 1], fS[64 + j]);
    }

    for (int k = 0; k < NSUB; ++k) {             // rolled; 16 dual steps/iter
        ckpt(A,  ckS, k,        tid);
        ckpt(Bc, ckS, NSUB + k, tid);
        const int baseA = HF + (k << 4);         // 8 + 16k
        const int baseB = baseA + 64;            // 72 + 16k
        #pragma unroll
        for (int j = 0; j < 16; ++j) {
            fstep(A,  sA[baseA + j + 1], fS[baseA + j]);
            fstep(Bc, sA[baseB + j + 1], fS[baseB + j]);
        }
    }

    // ===== phase 2: DUAL backward, tiles descending per sub-chain =====
    float uA = 0.0f, uB = 0.0f;
    float* ob = out + (size_t)(row0 + tid) * N_COLSK + s;

    // k = 4: halo tiles (no store)
    tile16<false>(sA, fS, HF + 64,      ckS[4 * TPB + tid], ckS[CKDP + 4 * TPB + tid], uA, nullptr);
    tile16<false>(sA, fS, HF + 64 + 64, ckS[9 * TPB + tid], ckS[CKDP + 9 * TPB + tid], uB, nullptr);

    for (int k = 3; k >= 0; --k) {               // rolled; dual owned tiles
        const int baseA = HF + (k << 4);
        tile16<true>(sA, fS, baseA,
                     ckS[k * TPB + tid], ckS[CKDP + k * TPB + tid],
                     uA, ob + (k << 4));
        tile16<true>(sA, fS, baseA + 64,
                     ckS[(NSUB + k) * TPB + tid], ckS[CKDP + (NSUB + k) * TPB + tid],
                     uB, ob + 64 + (k << 4));
    }
}

extern "C" void kernel_launch(void* const* d_in, const int* in_sizes, int n_in,
                              void* d_out, int out_size)
{
    const float* alpha = (const float*)d_in[0];
    const float* f     = (const float*)d_in[1];
    float* out         = (float*)d_out;

    static int smem_set = 0;
    if (!smem_set) {
        cudaFuncSetAttribute(thomas_chunk_kernel,
                             cudaFuncAttributeMaxDynamicSharedMemorySize,
                             SMEM_BYTES);
        smem_set = 1;
    }

    dim3 grid(N_COLSK / L_OWN, 2048 / TPB);      // (64, 16)
    thomas_chunk_kernel<<<grid, TPB, SMEM_BYTES>>>(alpha, f, out);
}